// round 16
// baseline (speedup 1.0000x reference)
#include <cuda_runtime.h>
#include <cuda_bf16.h>
#include <cstdint>
#include <cstddef>

// Problem constants (fixed by the reference)
#define BB 256
#define CC 32
#define HH 64
#define WW 64
#define PW 68           // padded width/height (2-px zero ring for 5x5 SAME)
#define PIMG (PW*PW)    // 4624

#define CHUNK3 16       // conv3k channel chunk

// conv HMMA tiling: 256 pixels per CTA (2 m16-tile groups of 128)
#define NPT  18         // 256-pixel tiles covering [128, 4736)
#define AR   532        // A tile rows: 256 + 2*138 halo

// ---------------------------------------------------------------------------
// Device-global scratch (allocation-free rule: __device__ globals only).
// ---------------------------------------------------------------------------
__device__ float    g_y2  [(size_t)BB * 64 * PIMG];   // conv2 output, padded
__device__ unsigned g_ahi0[(size_t)BB * PIMG * 16];   // rotate out hi [b][pix][c/2]
__device__ unsigned g_alo0[(size_t)BB * PIMG * 16];   // rotate out lo
__device__ unsigned g_ahi [(size_t)BB * PIMG * 32];   // conv1 out hi  [b][pix][c/2]
__device__ unsigned g_alo [(size_t)BB * PIMG * 32];   // conv1 out lo
__device__ unsigned g_wbf0[2 * 25 * 64 * 16];         // w0: [split][pos][oc][cin/2]
__device__ unsigned g_wbf1[2 * 25 * 64 * 32];         // w1: [split][pos][oc][cin/2]

// ---------------------------------------------------------------------------
// Helpers
// ---------------------------------------------------------------------------
// Fragment-pair permutation of cin-pair word index: places (8kk+t, 8kk+t+4)
// adjacent so MMA fragment pairs load as single LDS.64.
__device__ __forceinline__ int perm_cp(int cp) {
    return (cp & ~7) + ((cp & 3) * 2) + ((cp >> 2) & 1);
}

// Ampere-lineage bf16 tensor-core MMA (ISA-portable, valid on sm_100 target).
__device__ __forceinline__ void mma_bf16(float* c,
                                         unsigned a0, unsigned a1,
                                         unsigned a2, unsigned a3,
                                         unsigned b0, unsigned b1) {
    asm volatile(
        "mma.sync.aligned.m16n8k16.row.col.f32.bf16.bf16.f32 "
        "{%0,%1,%2,%3}, {%4,%5,%6,%7}, {%8,%9}, {%0,%1,%2,%3};"
        : "+f"(c[0]), "+f"(c[1]), "+f"(c[2]), "+f"(c[3])
        : "r"(a0), "r"(a1), "r"(a2), "r"(a3), "r"(b0), "r"(b1));
}

__device__ __forceinline__ unsigned pack_split_hi(float v0, float v1) {
    __nv_bfloat16 h0 = __float2bfloat16(v0);
    __nv_bfloat16 h1 = __float2bfloat16(v1);
    return (unsigned)__bfloat16_as_ushort(h0)
         | ((unsigned)__bfloat16_as_ushort(h1) << 16);
}
__device__ __forceinline__ unsigned pack_split_lo(float v0, float v1) {
    __nv_bfloat16 h0 = __float2bfloat16(v0);
    __nv_bfloat16 h1 = __float2bfloat16(v1);
    __nv_bfloat16 l0 = __float2bfloat16(v0 - __bfloat162float(h0));
    __nv_bfloat16 l1 = __float2bfloat16(v1 - __bfloat162float(h1));
    return (unsigned)__bfloat16_as_ushort(l0)
         | ((unsigned)__bfloat16_as_ushort(l1) << 16);
}

// ---------------------------------------------------------------------------
// Kernel 1: rotation -> bf16 hi/lo split, PIXEL-MAJOR [b][pix][16 words],
// words in perm_cp order. Block = (b, padded row). Full padded image (ring=0).
// ---------------------------------------------------------------------------
__global__ void rotate_kernel(const float* __restrict__ xin,
                              unsigned* __restrict__ ahi0,
                              unsigned* __restrict__ alo0)
{
    __shared__ float rows[CC * WW];
    __shared__ float cosv[CC], sinv[CC];

    const int b  = blockIdx.x / PW;
    const int py = blockIdx.x - b * PW;
    const int tid = threadIdx.x;

    for (int i = tid; i < CC * WW; i += 256)
        rows[i] = xin[(size_t)b * (CC * WW) + i];
    if (tid < CC) {
        const float ang = (-180.0f / 32.0f) * (float)tid * 0.017453292519943295f;
        sincosf(ang, &sinv[tid], &cosv[tid]);
    }
    __syncthreads();

    const int y = py - 2;
    const float yy = (float)y - 31.5f;

    for (int i = tid; i < PW * 16; i += 256) {
        const int px = i >> 4;
        const int cp = i & 15;
        const int x = px - 2;
        float v[2];
#pragma unroll
        for (int j = 0; j < 2; ++j) {
            const int c = 2 * cp + j;
            float val = 0.f;
            if ((unsigned)y < 64u && (unsigned)x < 64u) {
                const float co = cosv[c], si = sinv[c];
                const float xx = (float)x - 31.5f;
                const float xs = co * xx + si * yy + 31.5f;
                const float ys = co * yy - si * xx + 31.5f;
                const float x0f = floorf(xs);
                const float y0f = floorf(ys);
                const int x0  = (int)x0f;
                const int y0i = (int)y0f;
                const float wx1 = xs - x0f, wx0 = 1.f - wx1;
                const float wy1 = ys - y0f, wy0 = 1.f - wy1;
                float fy = 0.f;
                if ((unsigned)y0i       < 64u) fy += wy0;
                if ((unsigned)(y0i + 1) < 64u) fy += wy1;
                float fx = 0.f;
                if ((unsigned)x0       < 64u) fx += wx0 * rows[c * WW + x0];
                if ((unsigned)(x0 + 1) < 64u) fx += wx1 * rows[c * WW + x0 + 1];
                val = fy * fx;
            }
            v[j] = val;
        }
        const size_t o = ((size_t)b * PIMG + py * PW + px) * 16 + perm_cp(cp);
        ahi0[o] = pack_split_hi(v[0], v[1]);
        alo0[o] = pack_split_lo(v[0], v[1]);
    }
}

// ---------------------------------------------------------------------------
// Ring zeroing helpers.
// ---------------------------------------------------------------------------
__device__ __forceinline__ int ring_off(int p) {
    int off;
    if (p < 136)        off = p;                         // rows 0,1
    else if (p < 272)   off = 66 * PW + (p - 136);       // rows 66,67
    else {
        const int q = p - 272;
        const int r = 2 + (q >> 2);                      // rows 2..65
        const int cc4 = q & 3;
        off = r * PW + ((cc4 < 2) ? cc4 : 64 + cc4);     // cols 0,1,66,67
    }
    return off;
}

__global__ void zb_a(unsigned* __restrict__ hi, unsigned* __restrict__ lo)
{
    const int b = blockIdx.x;
    for (int i = threadIdx.x; i < 528 * 32; i += 256) {
        const int pi = i >> 5, w = i & 31;
        const size_t o = ((size_t)b * PIMG + ring_off(pi)) * 32 + w;
        hi[o] = 0u;
        lo[o] = 0u;
    }
}

__global__ void zb_y2(float* __restrict__ a)
{
    const int bc = blockIdx.x;          // b*64 + ch
    float* pa = a + (size_t)bc * PIMG;
    for (int p = threadIdx.x; p < 528; p += blockDim.x)
        pa[ring_off(p)] = 0.f;
}

// ---------------------------------------------------------------------------
// Weight pack: w[oc][cin][5][5] fp32 -> [split][pos][oc][KW words] bf16
// hi/lo split, cin pairs in perm_cp order.
// ---------------------------------------------------------------------------
template <int CIN>
__global__ void wprep_kernel(const float* __restrict__ w, unsigned* __restrict__ dst)
{
    constexpr int KW = CIN / 2;
    const int pos = blockIdx.x;     // 0..24
    for (int i = threadIdx.x; i < 64 * KW; i += blockDim.x) {
        const int oc = i / KW;
        const int cp = i - oc * KW;
        const float v0 = w[((size_t)oc * CIN + 2 * cp)     * 25 + pos];
        const float v1 = w[((size_t)oc * CIN + 2 * cp + 1) * 25 + pos];
        const int o = oc * KW + perm_cp(cp);
        dst[(0 * 25 + pos) * (64 * KW) + o] = pack_split_hi(v0, v1);
        dst[(1 * 25 + pos) * (64 * KW) + o] = pack_split_lo(v0, v1);
    }
}

// ---------------------------------------------------------------------------
// 5x5 conv via mma.sync (bf16 hi/lo split, fp32 acc), CIN = 2*KW -> 64 oc.
// CTA = 256 pixels (2 m-tile groups of 128) x 64 oc. Warp -> m16 rows
// {wid*16, wid*16+128}; 8 n8 oc-tiles; acc[2][8][4].
// Fragment pairs are single LDS.64 (perm_cp layout); B loaded once per
// (s,kk,n8) and reused for both m-tiles. ASTR conflict-free for 64b LDS.
// ---------------------------------------------------------------------------
template <int KW, bool SPLITOUT>
__global__ void __launch_bounds__(256, 1)
conv_hmma(const unsigned* __restrict__ ahi,   // [B][4624][KW] perm order
          const unsigned* __restrict__ alo,
          const unsigned* __restrict__ wbf,   // [2][25][64][KW] perm order
          const float* __restrict__ bias,     // [64]
          float* __restrict__ outf,           // [B][64][4624] (if !SPLITOUT)
          unsigned* __restrict__ ohi,         // [B][4624][32]  (if SPLITOUT)
          unsigned* __restrict__ olo)
{
    constexpr int QW    = KW / 4;             // uint4 per row
    constexpr int KSTEP = KW / 8;             // k16 steps
    constexpr int ASTR  = (KW == 16) ? 24 : 40;   // conflict-free 64b strides

    extern __shared__ float smem[];
    float*    sbias = smem;
    unsigned* sA    = (unsigned*)smem + 64;            // [2][AR][ASTR]
    unsigned* sB    = sA + 2 * AR * ASTR;              // [2][64][ASTR]

    const int tid  = threadIdx.x;
    const int wid  = tid >> 5;
    const int lane = tid & 31;
    const int g    = lane >> 2;
    const int t    = lane & 3;

    const int b  = blockIdx.x / NPT;
    const int tt = blockIdx.x - b * NPT;
    const int P0 = 128 + 256 * tt;

    if (tid < 64) sbias[tid] = bias[tid];

    // ---- load A tile (both splits): rows P0-138 .. P0+393, zero-guarded ----
#pragma unroll 1
    for (int sp = 0; sp < 2; ++sp) {
        const uint4* src = (const uint4*)((sp ? alo : ahi) + (size_t)b * PIMG * KW);
        unsigned* dst = sA + sp * (AR * ASTR);
#pragma unroll 1
        for (int i = tid; i < AR * QW; i += 256) {
            const int r = i / QW, q4 = i - r * QW;
            const int p = P0 - 138 + r;
            uint4 v = make_uint4(0, 0, 0, 0);
            if (p >= 0 && p < PIMG) v = src[(size_t)p * QW + q4];
            *(uint4*)(dst + r * ASTR + 4 * q4) = v;
        }
    }

    float acc[2][8][4];
#pragma unroll
    for (int mt = 0; mt < 2; ++mt)
#pragma unroll
        for (int n8 = 0; n8 < 8; ++n8)
#pragma unroll
            for (int j = 0; j < 4; ++j) acc[mt][n8][j] = 0.f;

    // ---- B prefetch regs covering [2][64][KW] ----
    constexpr int NBV = QW / 2;               // uint4 per thread
    const uint4* wq = (const uint4*)wbf;
    uint4 vr[NBV];
#pragma unroll
    for (int j = 0; j < NBV; ++j) {
        const int i = tid + j * 256;
        const int s = i / (64 * QW), rr = i - s * (64 * QW);
        vr[j] = wq[(size_t)(s * 25 + 0) * (64 * QW) + rr];
    }

#pragma unroll 1
    for (int pos = 0; pos < 25; ++pos) {
        __syncthreads();   // previous compute done reading sB
#pragma unroll
        for (int j = 0; j < NBV; ++j) {
            const int i = tid + j * 256;
            const int s = i / (64 * QW), rr = i - s * (64 * QW);
            const int row = rr / QW, q4 = rr - row * QW;
            *(uint4*)(sB + s * (64 * ASTR) + row * ASTR + 4 * q4) = vr[j];
        }
        __syncthreads();
        if (pos < 24) {
#pragma unroll
            for (int j = 0; j < NBV; ++j) {
                const int i = tid + j * 256;
                const int s = i / (64 * QW), rr = i - s * (64 * QW);
                vr[j] = wq[(size_t)(s * 25 + pos + 1) * (64 * QW) + rr];
            }
        }

        const int ky = pos / 5, kx = pos - 5 * ky;
        const int rowoff = 138 + (ky - 2) * PW + (kx - 2);
        const int arow = wid * 16 + rowoff + g;

#pragma unroll
        for (int s = 0; s < 3; ++s) {
            // splits: 0: Ah*Bh, 1: Ah*Bl, 2: Al*Bh
            const unsigned* As = sA + ((s == 2) ? AR * ASTR : 0);
            const unsigned* Bs = sB + ((s == 1) ? 64 * ASTR : 0);
#pragma unroll
            for (int kk = 0; kk < KSTEP; ++kk) {
                uint2 a02[2], a13[2];
#pragma unroll
                for (int mt = 0; mt < 2; ++mt) {
                    const unsigned* ap = As + (arow + 128 * mt) * ASTR
                                            + 8 * kk + 2 * t;
                    a02[mt] = *(const uint2*)ap;
                    a13[mt] = *(const uint2*)(ap + 8 * ASTR);
                }
#pragma unroll
                for (int n8 = 0; n8 < 8; ++n8) {
                    const uint2 b01 = *(const uint2*)
                        (Bs + (n8 * 8 + g) * ASTR + 8 * kk + 2 * t);
#pragma unroll
                    for (int mt = 0; mt < 2; ++mt)
                        mma_bf16(acc[mt][n8],
                                 a02[mt].x, a13[mt].x, a02[mt].y, a13[mt].y,
                                 b01.x, b01.y);
                }
            }
        }
    }

    // ---- epilogue: bias + ReLU, interior pixels only ----
#pragma unroll
    for (int mt = 0; mt < 2; ++mt) {
        const int p_lo = P0 + 128 * mt + wid * 16 + g;
        const int p_hi = p_lo + 8;
        const int ylo = p_lo / PW, xlo = p_lo - ylo * PW;
        const int yhi = p_hi / PW, xhi = p_hi - yhi * PW;
        const bool v_lo = (ylo >= 2 && ylo < 66 && xlo >= 2 && xlo < 66);
        const bool v_hi = (yhi >= 2 && yhi < 66 && xhi >= 2 && xhi < 66);

        if constexpr (SPLITOUT) {
            unsigned* hb = ohi + (size_t)b * PIMG * 32;
            unsigned* lb = olo + (size_t)b * PIMG * 32;
#pragma unroll
            for (int n8 = 0; n8 < 8; ++n8) {
                const int oc = n8 * 8 + 2 * t;
                const float bv0 = sbias[oc], bv1 = sbias[oc + 1];
                const int widx = perm_cp(n8 * 4 + t);
                if (v_lo) {
                    const float u0 = fmaxf(acc[mt][n8][0] + bv0, 0.f);
                    const float u1 = fmaxf(acc[mt][n8][1] + bv1, 0.f);
                    hb[(size_t)p_lo * 32 + widx] = pack_split_hi(u0, u1);
                    lb[(size_t)p_lo * 32 + widx] = pack_split_lo(u0, u1);
                }
                if (v_hi) {
                    const float u0 = fmaxf(acc[mt][n8][2] + bv0, 0.f);
                    const float u1 = fmaxf(acc[mt][n8][3] + bv1, 0.f);
                    hb[(size_t)p_hi * 32 + widx] = pack_split_hi(u0, u1);
                    lb[(size_t)p_hi * 32 + widx] = pack_split_lo(u0, u1);
                }
            }
        } else {
            float* ob = outf + (size_t)b * 64 * PIMG;
#pragma unroll
            for (int n8 = 0; n8 < 8; ++n8) {
                const int oc = n8 * 8 + 2 * t;
                const float bv0 = sbias[oc], bv1 = sbias[oc + 1];
                if (v_lo) {
                    ob[(size_t)oc * PIMG + p_lo]       = fmaxf(acc[mt][n8][0] + bv0, 0.f);
                    ob[(size_t)(oc + 1) * PIMG + p_lo] = fmaxf(acc[mt][n8][1] + bv1, 0.f);
                }
                if (v_hi) {
                    ob[(size_t)oc * PIMG + p_hi]       = fmaxf(acc[mt][n8][2] + bv0, 0.f);
                    ob[(size_t)(oc + 1) * PIMG + p_hi] = fmaxf(acc[mt][n8][3] + bv1, 0.f);
                }
            }
        }
    }
}

// ---------------------------------------------------------------------------
// Final 5x5 conv, 64 -> 1, writes d_out (B,64,64).
// ---------------------------------------------------------------------------
__global__ void __launch_bounds__(256, 4)
conv3k(const float* __restrict__ in,
       const float* __restrict__ w2,
       const float* __restrict__ b2,
       float* __restrict__ out)
{
    extern __shared__ float smem[];
    float* tile = smem;
    float* ws   = smem + CHUNK3 * 8 * PW;

    const int blk   = blockIdx.x;
    const int ytile = blk & 15;
    const int b     = blk >> 4;
    const int y0    = ytile * 4;

    for (int i = threadIdx.x; i < 1600; i += 256) ws[i] = w2[i];

    const int yr = threadIdx.x >> 6;
    const int x  = threadIdx.x & 63;
    float acc = b2[0];

#pragma unroll 1
    for (int chunk = 0; chunk < 64 / CHUNK3; ++chunk) {
        __syncthreads();
        const float* src = in + ((size_t)b * 64 + chunk * CHUNK3) * PIMG
                              + (size_t)y0 * PW;
        for (int i = threadIdx.x; i < CHUNK3 * 8 * PW; i += 256) {
            const int ch = i / (8 * PW);
            const int r  = i - ch * (8 * PW);
            tile[i] = src[(size_t)ch * PIMG + r];
        }
        __syncthreads();

#pragma unroll 1
        for (int cl = 0; cl < CHUNK3; ++cl) {
            const float* t  = tile + cl * (8 * PW) + yr * PW + x;
            const float* wc = ws + (chunk * CHUNK3 + cl) * 25;
#pragma unroll
            for (int ky = 0; ky < 5; ++ky)
#pragma unroll
                for (int kx = 0; kx < 5; ++kx)
                    acc += wc[ky * 5 + kx] * t[ky * PW + kx];
        }
    }
    out[(size_t)b * 4096 + (size_t)(y0 + yr) * 64 + x] = acc;
}

// ---------------------------------------------------------------------------
// kernel_launch (graph-capturable)
// ---------------------------------------------------------------------------
extern "C" void kernel_launch(void* const* d_in, const int* in_sizes, int n_in,
                              void* d_out, int out_size)
{
    (void)in_sizes; (void)n_in; (void)out_size;

    const float* x  = (const float*)d_in[0];
    const float* w0 = (const float*)d_in[1];
    const float* b0 = (const float*)d_in[2];
    const float* w1 = (const float*)d_in[3];
    const float* b1 = (const float*)d_in[4];
    const float* w2 = (const float*)d_in[5];
    const float* b2 = (const float*)d_in[6];
    float* out = (float*)d_out;

    void *py2, *pahi0, *palo0, *pahi, *palo, *pwbf0, *pwbf1;
    cudaGetSymbolAddress(&py2,   g_y2);
    cudaGetSymbolAddress(&pahi0, g_ahi0);
    cudaGetSymbolAddress(&palo0, g_alo0);
    cudaGetSymbolAddress(&pahi,  g_ahi);
    cudaGetSymbolAddress(&palo,  g_alo);
    cudaGetSymbolAddress(&pwbf0, g_wbf0);
    cudaGetSymbolAddress(&pwbf1, g_wbf1);

    constexpr int SMEM_C1 = (64 + 2 * AR * 24 + 2 * 64 * 24) * 4;  // 114,688 B
    constexpr int SMEM_C2 = (64 + 2 * AR * 40 + 2 * 64 * 40) * 4;  // 190,976 B
    constexpr int SMEM3   = (CHUNK3 * 8 * PW + 1600) * 4;          //  41,216 B

    cudaFuncSetAttribute((const void*)conv_hmma<16, true>,
                         cudaFuncAttributeMaxDynamicSharedMemorySize, SMEM_C1);
    cudaFuncSetAttribute((const void*)conv_hmma<32, false>,
                         cudaFuncAttributeMaxDynamicSharedMemorySize, SMEM_C2);
    cudaFuncSetAttribute((const void*)conv3k,
                         cudaFuncAttributeMaxDynamicSharedMemorySize, SMEM3);

    rotate_kernel<<<BB * PW, 256>>>(x, (unsigned*)pahi0, (unsigned*)palo0);
    zb_a<<<BB, 256>>>((unsigned*)pahi, (unsigned*)palo);
    zb_y2<<<BB * 64, 256>>>((float*)py2);
    wprep_kernel<32><<<25, 256>>>(w0, (unsigned*)pwbf0);
    wprep_kernel<64><<<25, 256>>>(w1, (unsigned*)pwbf1);

    conv_hmma<16, true><<<BB * NPT, 256, SMEM_C1>>>(
        (const unsigned*)pahi0, (const unsigned*)palo0,
        (const unsigned*)pwbf0, b0,
        nullptr, (unsigned*)pahi, (unsigned*)palo);

    conv_hmma<32, false><<<BB * NPT, 256, SMEM_C2>>>(
        (const unsigned*)pahi, (const unsigned*)palo,
        (const unsigned*)pwbf1, b1,
        (float*)py2, nullptr, nullptr);

    conv3k<<<BB * 16, 256, SMEM3>>>((const float*)py2, w2, b2, out);
}

// round 17
// speedup vs baseline: 1.0567x; 1.0567x over previous
#include <cuda_runtime.h>
#include <cuda_bf16.h>
#include <cstdint>
#include <cstddef>

// Problem constants (fixed by the reference)
#define BB 256
#define CC 32
#define HH 64
#define WW 64
#define PW 68           // padded width/height (2-px zero ring for 5x5 SAME)
#define PIMG (PW*PW)    // 4624

#define CHUNK3 16       // conv3k channel chunk

// ---------------------------------------------------------------------------
// Device-global scratch (allocation-free rule: __device__ globals only).
// ---------------------------------------------------------------------------
__device__ float    g_y2  [(size_t)BB * 64 * PIMG];   // conv2 output, padded
__device__ unsigned g_ahi0[(size_t)BB * PIMG * 16];   // rotate out hi [b][pix][c/2]
__device__ unsigned g_alo0[(size_t)BB * PIMG * 16];   // rotate out lo
__device__ unsigned g_ahi [(size_t)BB * PIMG * 32];   // conv1 out hi  [b][pix][c/2]
__device__ unsigned g_alo [(size_t)BB * PIMG * 32];   // conv1 out lo
__device__ unsigned g_wbf0[2 * 25 * 64 * 16];         // w0: [split][pos][oc][cin/2]
__device__ unsigned g_wbf1[2 * 25 * 64 * 32];         // w1: [split][pos][oc][cin/2]

// ---------------------------------------------------------------------------
// Helpers
// ---------------------------------------------------------------------------
// Fragment-pair permutation of cin-pair word index: places (8kk+t, 8kk+t+4)
// adjacent so MMA fragment pairs load as single LDS.64.
__device__ __forceinline__ int perm_cp(int cp) {
    return (cp & ~7) + ((cp & 3) * 2) + ((cp >> 2) & 1);
}

// Ampere-lineage bf16 tensor-core MMA (ISA-portable, valid on sm_100 target).
__device__ __forceinline__ void mma_bf16(float* c,
                                         unsigned a0, unsigned a1,
                                         unsigned a2, unsigned a3,
                                         unsigned b0, unsigned b1) {
    asm volatile(
        "mma.sync.aligned.m16n8k16.row.col.f32.bf16.bf16.f32 "
        "{%0,%1,%2,%3}, {%4,%5,%6,%7}, {%8,%9}, {%0,%1,%2,%3};"
        : "+f"(c[0]), "+f"(c[1]), "+f"(c[2]), "+f"(c[3])
        : "r"(a0), "r"(a1), "r"(a2), "r"(a3), "r"(b0), "r"(b1));
}

__device__ __forceinline__ unsigned pack_split_hi(float v0, float v1) {
    __nv_bfloat16 h0 = __float2bfloat16(v0);
    __nv_bfloat16 h1 = __float2bfloat16(v1);
    return (unsigned)__bfloat16_as_ushort(h0)
         | ((unsigned)__bfloat16_as_ushort(h1) << 16);
}
__device__ __forceinline__ unsigned pack_split_lo(float v0, float v1) {
    __nv_bfloat16 h0 = __float2bfloat16(v0);
    __nv_bfloat16 h1 = __float2bfloat16(v1);
    __nv_bfloat16 l0 = __float2bfloat16(v0 - __bfloat162float(h0));
    __nv_bfloat16 l1 = __float2bfloat16(v1 - __bfloat162float(h1));
    return (unsigned)__bfloat16_as_ushort(l0)
         | ((unsigned)__bfloat16_as_ushort(l1) << 16);
}

// ---------------------------------------------------------------------------
// Kernel 1: rotation -> bf16 hi/lo split, PIXEL-MAJOR [b][pix][16 words],
// words in perm_cp order. Block = (b, padded row). Full padded image (ring=0).
// ---------------------------------------------------------------------------
__global__ void rotate_kernel(const float* __restrict__ xin,
                              unsigned* __restrict__ ahi0,
                              unsigned* __restrict__ alo0)
{
    __shared__ float rows[CC * WW];
    __shared__ float cosv[CC], sinv[CC];

    const int b  = blockIdx.x / PW;
    const int py = blockIdx.x - b * PW;
    const int tid = threadIdx.x;

    for (int i = tid; i < CC * WW; i += 256)
        rows[i] = xin[(size_t)b * (CC * WW) + i];
    if (tid < CC) {
        const float ang = (-180.0f / 32.0f) * (float)tid * 0.017453292519943295f;
        sincosf(ang, &sinv[tid], &cosv[tid]);
    }
    __syncthreads();

    const int y = py - 2;
    const float yy = (float)y - 31.5f;

    for (int i = tid; i < PW * 16; i += 256) {
        const int px = i >> 4;
        const int cp = i & 15;
        const int x = px - 2;
        float v[2];
#pragma unroll
        for (int j = 0; j < 2; ++j) {
            const int c = 2 * cp + j;
            float val = 0.f;
            if ((unsigned)y < 64u && (unsigned)x < 64u) {
                const float co = cosv[c], si = sinv[c];
                const float xx = (float)x - 31.5f;
                const float xs = co * xx + si * yy + 31.5f;
                const float ys = co * yy - si * xx + 31.5f;
                const float x0f = floorf(xs);
                const float y0f = floorf(ys);
                const int x0  = (int)x0f;
                const int y0i = (int)y0f;
                const float wx1 = xs - x0f, wx0 = 1.f - wx1;
                const float wy1 = ys - y0f, wy0 = 1.f - wy1;
                float fy = 0.f;
                if ((unsigned)y0i       < 64u) fy += wy0;
                if ((unsigned)(y0i + 1) < 64u) fy += wy1;
                float fx = 0.f;
                if ((unsigned)x0       < 64u) fx += wx0 * rows[c * WW + x0];
                if ((unsigned)(x0 + 1) < 64u) fx += wx1 * rows[c * WW + x0 + 1];
                val = fy * fx;
            }
            v[j] = val;
        }
        const size_t o = ((size_t)b * PIMG + py * PW + px) * 16 + perm_cp(cp);
        ahi0[o] = pack_split_hi(v[0], v[1]);
        alo0[o] = pack_split_lo(v[0], v[1]);
    }
}

// ---------------------------------------------------------------------------
// Ring zeroing (conv1 output buffers + conv2 output buffer, one kernel).
// ---------------------------------------------------------------------------
__device__ __forceinline__ int ring_off(int p) {
    int off;
    if (p < 136)        off = p;                         // rows 0,1
    else if (p < 272)   off = 66 * PW + (p - 136);       // rows 66,67
    else {
        const int q = p - 272;
        const int r = 2 + (q >> 2);                      // rows 2..65
        const int cc4 = q & 3;
        off = r * PW + ((cc4 < 2) ? cc4 : 64 + cc4);     // cols 0,1,66,67
    }
    return off;
}

__global__ void zb_all(unsigned* __restrict__ hi, unsigned* __restrict__ lo,
                       float* __restrict__ y2)
{
    const int b = blockIdx.x;
    for (int i = threadIdx.x; i < 528 * 32; i += 256) {
        const int pi = i >> 5, w = i & 31;
        const size_t o = ((size_t)b * PIMG + ring_off(pi)) * 32 + w;
        hi[o] = 0u;
        lo[o] = 0u;
    }
    // y2 ring: 64 channels x 528 ring pixels
    float* pb = y2 + (size_t)b * 64 * PIMG;
    for (int i = threadIdx.x; i < 64 * 528; i += 256) {
        const int ch = i / 528, p = i - ch * 528;
        pb[(size_t)ch * PIMG + ring_off(p)] = 0.f;
    }
}

// ---------------------------------------------------------------------------
// Weight pack: w[oc][cin][5][5] fp32 -> [split][pos][oc][KW words] bf16
// hi/lo split, cin pairs in perm_cp order.
// ---------------------------------------------------------------------------
template <int CIN>
__global__ void wprep_kernel(const float* __restrict__ w, unsigned* __restrict__ dst)
{
    constexpr int KW = CIN / 2;
    const int pos = blockIdx.x;     // 0..24
    for (int i = threadIdx.x; i < 64 * KW; i += blockDim.x) {
        const int oc = i / KW;
        const int cp = i - oc * KW;
        const float v0 = w[((size_t)oc * CIN + 2 * cp)     * 25 + pos];
        const float v1 = w[((size_t)oc * CIN + 2 * cp + 1) * 25 + pos];
        const int o = oc * KW + perm_cp(cp);
        dst[(0 * 25 + pos) * (64 * KW) + o] = pack_split_hi(v0, v1);
        dst[(1 * 25 + pos) * (64 * KW) + o] = pack_split_lo(v0, v1);
    }
}

// ---------------------------------------------------------------------------
// 5x5 conv via mma.sync (bf16 hi/lo split, fp32 acc), CIN = 2*KW -> 64 oc.
// CTA = 128*MTILES pixels x 64 oc. Warp -> m16 rows {wid*16 + 128*mt}.
// Fragment pairs load as single LDS.64 (perm_cp layout); B fragments are
// loaded once per (s,kk,n8) and reused across m-tiles.
// conv1: KW=16, MTILES=1 -> 90KB smem, 2 CTAs/SM.
// conv2: KW=32, MTILES=2 -> 191KB smem, 1 CTA/SM, better B amortization.
// ---------------------------------------------------------------------------
template <int KW, int MTILES, bool SPLITOUT>
__global__ void __launch_bounds__(256, (KW == 16) ? 2 : 1)
conv_hmma(const unsigned* __restrict__ ahi,   // [B][4624][KW] perm order
          const unsigned* __restrict__ alo,
          const unsigned* __restrict__ wbf,   // [2][25][64][KW] perm order
          const float* __restrict__ bias,     // [64]
          float* __restrict__ outf,           // [B][64][4624] (if !SPLITOUT)
          unsigned* __restrict__ ohi,         // [B][4624][32]  (if SPLITOUT)
          unsigned* __restrict__ olo)
{
    constexpr int QW    = KW / 4;             // uint4 per row
    constexpr int KSTEP = KW / 8;             // k16 steps
    constexpr int ASTR  = (KW == 16) ? 24 : 40;   // conflict-free 64b strides
    constexpr int AR    = 128 * MTILES + 276;     // tile rows incl. halo
    constexpr int PIXT  = 128 * MTILES;

    extern __shared__ float smem[];
    float*    sbias = smem;
    unsigned* sA    = (unsigned*)smem + 64;            // [2][AR][ASTR]
    unsigned* sB    = sA + 2 * AR * ASTR;              // [2][64][ASTR]

    const int tid  = threadIdx.x;
    const int wid  = tid >> 5;
    const int lane = tid & 31;
    const int g    = lane >> 2;
    const int t    = lane & 3;

    const int NPT = (PIMG - 256 + PIXT - 1) / PIXT;   // tiles over [128, ...)
    const int b  = blockIdx.x / NPT;
    const int tt = blockIdx.x - b * NPT;
    const int P0 = 128 + PIXT * tt;

    if (tid < 64) sbias[tid] = bias[tid];

    // ---- load A tile (both splits): rows P0-138 .., zero-guarded ----
#pragma unroll 1
    for (int sp = 0; sp < 2; ++sp) {
        const uint4* src = (const uint4*)((sp ? alo : ahi) + (size_t)b * PIMG * KW);
        unsigned* dst = sA + sp * (AR * ASTR);
#pragma unroll 1
        for (int i = tid; i < AR * QW; i += 256) {
            const int r = i / QW, q4 = i - r * QW;
            const int p = P0 - 138 + r;
            uint4 v = make_uint4(0, 0, 0, 0);
            if (p >= 0 && p < PIMG) v = src[(size_t)p * QW + q4];
            *(uint4*)(dst + r * ASTR + 4 * q4) = v;
        }
    }

    float acc[MTILES][8][4];
#pragma unroll
    for (int mt = 0; mt < MTILES; ++mt)
#pragma unroll
        for (int n8 = 0; n8 < 8; ++n8)
#pragma unroll
            for (int j = 0; j < 4; ++j) acc[mt][n8][j] = 0.f;

    // ---- B prefetch regs covering [2][64][KW] ----
    constexpr int NBV = QW / 2;               // uint4 per thread
    const uint4* wq = (const uint4*)wbf;
    uint4 vr[NBV];
#pragma unroll
    for (int j = 0; j < NBV; ++j) {
        const int i = tid + j * 256;
        const int s = i / (64 * QW), rr = i - s * (64 * QW);
        vr[j] = wq[(size_t)(s * 25 + 0) * (64 * QW) + rr];
    }

#pragma unroll 1
    for (int pos = 0; pos < 25; ++pos) {
        __syncthreads();   // previous compute done reading sB
#pragma unroll
        for (int j = 0; j < NBV; ++j) {
            const int i = tid + j * 256;
            const int s = i / (64 * QW), rr = i - s * (64 * QW);
            const int row = rr / QW, q4 = rr - row * QW;
            *(uint4*)(sB + s * (64 * ASTR) + row * ASTR + 4 * q4) = vr[j];
        }
        __syncthreads();
        if (pos < 24) {
#pragma unroll
            for (int j = 0; j < NBV; ++j) {
                const int i = tid + j * 256;
                const int s = i / (64 * QW), rr = i - s * (64 * QW);
                vr[j] = wq[(size_t)(s * 25 + pos + 1) * (64 * QW) + rr];
            }
        }

        const int ky = pos / 5, kx = pos - 5 * ky;
        const int rowoff = 138 + (ky - 2) * PW + (kx - 2);
        const int arow = wid * 16 + rowoff + g;

#pragma unroll
        for (int s = 0; s < 3; ++s) {
            // splits: 0: Ah*Bh, 1: Ah*Bl, 2: Al*Bh
            const unsigned* As = sA + ((s == 2) ? AR * ASTR : 0);
            const unsigned* Bs = sB + ((s == 1) ? 64 * ASTR : 0);
#pragma unroll
            for (int kk = 0; kk < KSTEP; ++kk) {
                uint2 a02[MTILES], a13[MTILES];
#pragma unroll
                for (int mt = 0; mt < MTILES; ++mt) {
                    const unsigned* ap = As + (arow + 128 * mt) * ASTR
                                            + 8 * kk + 2 * t;
                    a02[mt] = *(const uint2*)ap;
                    a13[mt] = *(const uint2*)(ap + 8 * ASTR);
                }
#pragma unroll
                for (int n8 = 0; n8 < 8; ++n8) {
                    const uint2 b01 = *(const uint2*)
                        (Bs + (n8 * 8 + g) * ASTR + 8 * kk + 2 * t);
#pragma unroll
                    for (int mt = 0; mt < MTILES; ++mt)
                        mma_bf16(acc[mt][n8],
                                 a02[mt].x, a13[mt].x, a02[mt].y, a13[mt].y,
                                 b01.x, b01.y);
                }
            }
        }
    }

    // ---- epilogue: bias + ReLU, interior pixels only ----
#pragma unroll
    for (int mt = 0; mt < MTILES; ++mt) {
        const int p_lo = P0 + 128 * mt + wid * 16 + g;
        const int p_hi = p_lo + 8;
        const int ylo = p_lo / PW, xlo = p_lo - ylo * PW;
        const int yhi = p_hi / PW, xhi = p_hi - yhi * PW;
        const bool v_lo = (p_lo < PIMG) && (ylo >= 2 && ylo < 66 && xlo >= 2 && xlo < 66);
        const bool v_hi = (p_hi < PIMG) && (yhi >= 2 && yhi < 66 && xhi >= 2 && xhi < 66);

        if constexpr (SPLITOUT) {
            unsigned* hb = ohi + (size_t)b * PIMG * 32;
            unsigned* lb = olo + (size_t)b * PIMG * 32;
#pragma unroll
            for (int n8 = 0; n8 < 8; ++n8) {
                const int oc = n8 * 8 + 2 * t;
                const float bv0 = sbias[oc], bv1 = sbias[oc + 1];
                const int widx = perm_cp(n8 * 4 + t);
                if (v_lo) {
                    const float u0 = fmaxf(acc[mt][n8][0] + bv0, 0.f);
                    const float u1 = fmaxf(acc[mt][n8][1] + bv1, 0.f);
                    hb[(size_t)p_lo * 32 + widx] = pack_split_hi(u0, u1);
                    lb[(size_t)p_lo * 32 + widx] = pack_split_lo(u0, u1);
                }
                if (v_hi) {
                    const float u0 = fmaxf(acc[mt][n8][2] + bv0, 0.f);
                    const float u1 = fmaxf(acc[mt][n8][3] + bv1, 0.f);
                    hb[(size_t)p_hi * 32 + widx] = pack_split_hi(u0, u1);
                    lb[(size_t)p_hi * 32 + widx] = pack_split_lo(u0, u1);
                }
            }
        } else {
            float* ob = outf + (size_t)b * 64 * PIMG;
#pragma unroll
            for (int n8 = 0; n8 < 8; ++n8) {
                const int oc = n8 * 8 + 2 * t;
                const float bv0 = sbias[oc], bv1 = sbias[oc + 1];
                if (v_lo) {
                    ob[(size_t)oc * PIMG + p_lo]       = fmaxf(acc[mt][n8][0] + bv0, 0.f);
                    ob[(size_t)(oc + 1) * PIMG + p_lo] = fmaxf(acc[mt][n8][1] + bv1, 0.f);
                }
                if (v_hi) {
                    ob[(size_t)oc * PIMG + p_hi]       = fmaxf(acc[mt][n8][2] + bv0, 0.f);
                    ob[(size_t)(oc + 1) * PIMG + p_hi] = fmaxf(acc[mt][n8][3] + bv1, 0.f);
                }
            }
        }
    }
}

// ---------------------------------------------------------------------------
// Final 5x5 conv, 64 -> 1, writes d_out (B,64,64).
// ---------------------------------------------------------------------------
__global__ void __launch_bounds__(256, 4)
conv3k(const float* __restrict__ in,
       const float* __restrict__ w2,
       const float* __restrict__ b2,
       float* __restrict__ out)
{
    extern __shared__ float smem[];
    float* tile = smem;
    float* ws   = smem + CHUNK3 * 8 * PW;

    const int blk   = blockIdx.x;
    const int ytile = blk & 15;
    const int b     = blk >> 4;
    const int y0    = ytile * 4;

    for (int i = threadIdx.x; i < 1600; i += 256) ws[i] = w2[i];

    const int yr = threadIdx.x >> 6;
    const int x  = threadIdx.x & 63;
    float acc = b2[0];

#pragma unroll 1
    for (int chunk = 0; chunk < 64 / CHUNK3; ++chunk) {
        __syncthreads();
        const float* src = in + ((size_t)b * 64 + chunk * CHUNK3) * PIMG
                              + (size_t)y0 * PW;
        for (int i = threadIdx.x; i < CHUNK3 * 8 * PW; i += 256) {
            const int ch = i / (8 * PW);
            const int r  = i - ch * (8 * PW);
            tile[i] = src[(size_t)ch * PIMG + r];
        }
        __syncthreads();

#pragma unroll 1
        for (int cl = 0; cl < CHUNK3; ++cl) {
            const float* t  = tile + cl * (8 * PW) + yr * PW + x;
            const float* wc = ws + (chunk * CHUNK3 + cl) * 25;
#pragma unroll
            for (int ky = 0; ky < 5; ++ky)
#pragma unroll
                for (int kx = 0; kx < 5; ++kx)
                    acc += wc[ky * 5 + kx] * t[ky * PW + kx];
        }
    }
    out[(size_t)b * 4096 + (size_t)(y0 + yr) * 64 + x] = acc;
}

// ---------------------------------------------------------------------------
// kernel_launch (graph-capturable)
// ---------------------------------------------------------------------------
extern "C" void kernel_launch(void* const* d_in, const int* in_sizes, int n_in,
                              void* d_out, int out_size)
{
    (void)in_sizes; (void)n_in; (void)out_size;

    const float* x  = (const float*)d_in[0];
    const float* w0 = (const float*)d_in[1];
    const float* b0 = (const float*)d_in[2];
    const float* w1 = (const float*)d_in[3];
    const float* b1 = (const float*)d_in[4];
    const float* w2 = (const float*)d_in[5];
    const float* b2 = (const float*)d_in[6];
    float* out = (float*)d_out;

    void *py2, *pahi0, *palo0, *pahi, *palo, *pwbf0, *pwbf1;
    cudaGetSymbolAddress(&py2,   g_y2);
    cudaGetSymbolAddress(&pahi0, g_ahi0);
    cudaGetSymbolAddress(&palo0, g_alo0);
    cudaGetSymbolAddress(&pahi,  g_ahi);
    cudaGetSymbolAddress(&palo,  g_alo);
    cudaGetSymbolAddress(&pwbf0, g_wbf0);
    cudaGetSymbolAddress(&pwbf1, g_wbf1);

    // conv1: AR=404, ASTR=24 -> 90,112 B (2 CTAs/SM)
    constexpr int SMEM_C1 = (64 + 2 * 404 * 24 + 2 * 64 * 24) * 4;
    // conv2: AR=532, ASTR=40 -> 190,976 B (1 CTA/SM)
    constexpr int SMEM_C2 = (64 + 2 * 532 * 40 + 2 * 64 * 40) * 4;
    constexpr int SMEM3   = (CHUNK3 * 8 * PW + 1600) * 4;

    cudaFuncSetAttribute((const void*)conv_hmma<16, 1, true>,
                         cudaFuncAttributeMaxDynamicSharedMemorySize, SMEM_C1);
    cudaFuncSetAttribute((const void*)conv_hmma<32, 2, false>,
                         cudaFuncAttributeMaxDynamicSharedMemorySize, SMEM_C2);
    cudaFuncSetAttribute((const void*)conv3k,
                         cudaFuncAttributeMaxDynamicSharedMemorySize, SMEM3);

    rotate_kernel<<<BB * PW, 256>>>(x, (unsigned*)pahi0, (unsigned*)palo0);
    zb_all<<<BB, 256>>>((unsigned*)pahi, (unsigned*)palo, (float*)py2);
    wprep_kernel<32><<<25, 256>>>(w0, (unsigned*)pwbf0);
    wprep_kernel<64><<<25, 256>>>(w1, (unsigned*)pwbf1);

    // conv1: 128-px tiles -> 35 tiles; conv2: 256-px tiles -> 18 tiles
    conv_hmma<16, 1, true><<<BB * 35, 256, SMEM_C1>>>(
        (const unsigned*)pahi0, (const unsigned*)palo0,
        (const unsigned*)pwbf0, b0,
        nullptr, (unsigned*)pahi, (unsigned*)palo);

    conv_hmma<32, 2, false><<<BB * 18, 256, SMEM_C2>>>(
        (const unsigned*)pahi, (const unsigned*)palo,
        (const unsigned*)pwbf1, b1,
        (float*)py2, nullptr, nullptr);

    conv3k<<<BB * 16, 256, SMEM3>>>((const float*)py2, w2, b2, out);
}